// round 1
// baseline (speedup 1.0000x reference)
#include <cuda_runtime.h>
#include <cstdint>
#include <cstddef>

#define B4    4
#define NSEQ  4096
#define CDIM  1024
#define NH    16
#define HD    64
#define NBH   (B4*NH)

// Scratch (allowed: __device__ globals, no runtime allocation)
static __device__ float g_q [NBH * NSEQ * HD];   // [B,H,N,D] 64MB
static __device__ float g_k [NBH * NSEQ * HD];
static __device__ float g_v [NBH * NSEQ * HD];
static __device__ float g_kv[NBH * HD * HD];     // [B,H,D,D] 1MB
static __device__ float g_o [B4 * NSEQ * CDIM];  // [B,N,C]   64MB

__device__ __forceinline__ float tf32r(float x) {
    uint32_t u;
    asm("cvt.rna.tf32.f32 %0, %1;" : "=r"(u) : "f"(x));
    return __uint_as_float(u);
}

__device__ __forceinline__ void mma8(float c[4], const float a[4], const float b[2]) {
    const uint32_t* A  = reinterpret_cast<const uint32_t*>(a);
    const uint32_t* Bv = reinterpret_cast<const uint32_t*>(b);
    asm volatile(
        "mma.sync.aligned.m16n8k8.row.col.f32.tf32.tf32.f32 "
        "{%0,%1,%2,%3}, {%4,%5,%6,%7}, {%8,%9}, {%0,%1,%2,%3};\n"
        : "+f"(c[0]), "+f"(c[1]), "+f"(c[2]), "+f"(c[3])
        : "r"(A[0]), "r"(A[1]), "r"(A[2]), "r"(A[3]),
          "r"(Bv[0]), "r"(Bv[1]));
}

// ---------------------------------------------------------------------------
// C[m,o] = sum_k X[m,k] * W[o,k]   (X: [16384,1024] row-major, W: [1024,1024])
// MODE 0: scatter result into qkv buffer (sel picks q/k/v) in [B,H,N,D] layout.
// MODE 1: X is ignored (reads g_o), writes outp[m*CDIM+o] + bias[o].
// Tile: BM=128, BN=128, BK=16. 8 warps (2x4), warp tile 64x32, m16n8k8 tf32.
// ---------------------------------------------------------------------------
template<int MODE>
__global__ __launch_bounds__(256, 1)
void proj_kernel(const float* __restrict__ X, const float* __restrict__ W,
                 const float* __restrict__ bias, float* __restrict__ outp, int sel)
{
    __shared__ float sA[2][16][136];   // [k][m], pad 8 -> conflict-free frag reads
    __shared__ float sB[2][16][136];   // [k][n]

    const int tid    = threadIdx.x;
    const int lane   = tid & 31;
    const int warpId = tid >> 5;
    const int g  = lane >> 2;
    const int t  = lane & 3;
    const int wm = warpId & 1;   // 2 warps over M
    const int wn = warpId >> 1;  // 4 warps over N
    const int m0 = blockIdx.x * 128;
    const int n0 = blockIdx.y * 128;

    const int lrow = tid >> 2;        // 0..63 (and +64)
    const int lkc  = (tid & 3) * 4;   // 0,4,8,12

    const float* Xs = (MODE == 1) ? (const float*)g_o : X;
    const float* pa0 = Xs + (size_t)(m0 + lrow) * CDIM + lkc;
    const float* pb0 = W  + (size_t)(n0 + lrow) * CDIM + lkc;

    float4 rA0, rA1, rB0, rB1;

    float acc[4][4][4];
#pragma unroll
    for (int a = 0; a < 4; ++a)
#pragma unroll
        for (int b = 0; b < 4; ++b)
#pragma unroll
            for (int c = 0; c < 4; ++c) acc[a][b][c] = 0.f;

    auto fetch = [&](int kt) {
        const float* pa = pa0 + kt * 16;
        const float* pb = pb0 + kt * 16;
        rA0 = *reinterpret_cast<const float4*>(pa);
        rA1 = *reinterpret_cast<const float4*>(pa + 64 * CDIM);
        rB0 = *reinterpret_cast<const float4*>(pb);
        rB1 = *reinterpret_cast<const float4*>(pb + 64 * CDIM);
    };
    auto stage = [&](int bf) {
        sA[bf][lkc+0][lrow]    = tf32r(rA0.x);
        sA[bf][lkc+1][lrow]    = tf32r(rA0.y);
        sA[bf][lkc+2][lrow]    = tf32r(rA0.z);
        sA[bf][lkc+3][lrow]    = tf32r(rA0.w);
        sA[bf][lkc+0][lrow+64] = tf32r(rA1.x);
        sA[bf][lkc+1][lrow+64] = tf32r(rA1.y);
        sA[bf][lkc+2][lrow+64] = tf32r(rA1.z);
        sA[bf][lkc+3][lrow+64] = tf32r(rA1.w);
        sB[bf][lkc+0][lrow]    = tf32r(rB0.x);
        sB[bf][lkc+1][lrow]    = tf32r(rB0.y);
        sB[bf][lkc+2][lrow]    = tf32r(rB0.z);
        sB[bf][lkc+3][lrow]    = tf32r(rB0.w);
        sB[bf][lkc+0][lrow+64] = tf32r(rB1.x);
        sB[bf][lkc+1][lrow+64] = tf32r(rB1.y);
        sB[bf][lkc+2][lrow+64] = tf32r(rB1.z);
        sB[bf][lkc+3][lrow+64] = tf32r(rB1.w);
    };

    fetch(0); stage(0); __syncthreads();
    int buf = 0;
    for (int kt = 0; kt < 64; ++kt) {
        if (kt < 63) fetch(kt + 1);
#pragma unroll
        for (int ks = 0; ks < 2; ++ks) {
            const int kk = ks * 8;
            float af[4][4], bfr[4][2];
#pragma unroll
            for (int mi = 0; mi < 4; ++mi) {
                const int rm = wm * 64 + mi * 16 + g;
                af[mi][0] = sA[buf][kk + t][rm];
                af[mi][1] = sA[buf][kk + t][rm + 8];
                af[mi][2] = sA[buf][kk + t + 4][rm];
                af[mi][3] = sA[buf][kk + t + 4][rm + 8];
            }
#pragma unroll
            for (int ni = 0; ni < 4; ++ni) {
                const int cn = wn * 32 + ni * 8 + g;
                bfr[ni][0] = sB[buf][kk + t][cn];
                bfr[ni][1] = sB[buf][kk + t + 4][cn];
            }
#pragma unroll
            for (int mi = 0; mi < 4; ++mi)
#pragma unroll
                for (int ni = 0; ni < 4; ++ni)
                    mma8(acc[mi][ni], af[mi], bfr[ni]);
        }
        if (kt < 63) { stage(buf ^ 1); __syncthreads(); buf ^= 1; }
    }

    float* qkv = nullptr;
    if (MODE == 0) qkv = (sel == 0) ? g_q : (sel == 1) ? g_k : g_v;

#pragma unroll
    for (int mi = 0; mi < 4; ++mi) {
#pragma unroll
        for (int ni = 0; ni < 4; ++ni) {
            const int row = m0 + wm * 64 + mi * 16 + g;
            const int col = n0 + wn * 32 + ni * 8 + 2 * t;
            if (MODE == 0) {
                const int b = row >> 12, n = row & (NSEQ - 1);
                const int h = col >> 6,  d = col & (HD - 1);
                float* p = qkv + (((size_t)(b * NH + h) * NSEQ + n) * HD + d);
                *reinterpret_cast<float2*>(p) =
                    make_float2(acc[mi][ni][0], acc[mi][ni][1]);
                *reinterpret_cast<float2*>(p + 8 * HD) =
                    make_float2(acc[mi][ni][2], acc[mi][ni][3]);
            } else {
                const float b0v = bias[col], b1v = bias[col + 1];
                *reinterpret_cast<float2*>(outp + (size_t)row * CDIM + col) =
                    make_float2(acc[mi][ni][0] + b0v, acc[mi][ni][1] + b1v);
                *reinterpret_cast<float2*>(outp + (size_t)(row + 8) * CDIM + col) =
                    make_float2(acc[mi][ni][2] + b0v, acc[mi][ni][3] + b1v);
            }
        }
    }
}

// ---------------------------------------------------------------------------
// kv[bh][d][e] = 0.125 * sum_n k[bh][n][d] * v[bh][n][e]
// One block per bh. Tile 64x64, K(N)-chunks of 32, double-buffered.
// 8 warps (2x4), warp tile 32x16.
// ---------------------------------------------------------------------------
__global__ __launch_bounds__(256, 1)
void kv_kernel()
{
    __shared__ float sk[2][32][72];   // [n][d], pad 8
    __shared__ float sv[2][32][72];   // [n][e], pad 8
    const int bh = blockIdx.x;
    const float* Kp = g_k + (size_t)bh * NSEQ * HD;
    const float* Vp = g_v + (size_t)bh * NSEQ * HD;

    const int tid = threadIdx.x;
    const int lane = tid & 31, warpId = tid >> 5;
    const int g = lane >> 2, t = lane & 3;
    const int wm = warpId & 1, wn = warpId >> 1;

    const int lrow = tid >> 4;        // 0..15 (and +16)
    const int lc   = (tid & 15) * 4;  // 0..60

    float4 rk0, rk1, rv0, rv1;
    auto fetch = [&](int nt) {
        const size_t base = (size_t)(nt * 32 + lrow) * HD + lc;
        rk0 = *reinterpret_cast<const float4*>(Kp + base);
        rk1 = *reinterpret_cast<const float4*>(Kp + base + 16 * HD);
        rv0 = *reinterpret_cast<const float4*>(Vp + base);
        rv1 = *reinterpret_cast<const float4*>(Vp + base + 16 * HD);
    };
    auto cvt4 = [](float4 v) {
        return make_float4(tf32r(v.x), tf32r(v.y), tf32r(v.z), tf32r(v.w));
    };
    auto stage = [&](int bf) {
        *reinterpret_cast<float4*>(&sk[bf][lrow][lc])      = cvt4(rk0);
        *reinterpret_cast<float4*>(&sk[bf][lrow + 16][lc]) = cvt4(rk1);
        *reinterpret_cast<float4*>(&sv[bf][lrow][lc])      = cvt4(rv0);
        *reinterpret_cast<float4*>(&sv[bf][lrow + 16][lc]) = cvt4(rv1);
    };

    float acc[2][2][4];
#pragma unroll
    for (int a = 0; a < 2; ++a)
#pragma unroll
        for (int b = 0; b < 2; ++b)
#pragma unroll
            for (int c = 0; c < 4; ++c) acc[a][b][c] = 0.f;

    fetch(0); stage(0); __syncthreads();
    int buf = 0;
    for (int nt = 0; nt < 128; ++nt) {
        if (nt < 127) fetch(nt + 1);
#pragma unroll
        for (int ks = 0; ks < 4; ++ks) {
            const int kk = ks * 8;
            float af[2][4], bfr[2][2];
#pragma unroll
            for (int mi = 0; mi < 2; ++mi) {
                const int rd = wm * 32 + mi * 16 + g;
                af[mi][0] = sk[buf][kk + t][rd];
                af[mi][1] = sk[buf][kk + t][rd + 8];
                af[mi][2] = sk[buf][kk + t + 4][rd];
                af[mi][3] = sk[buf][kk + t + 4][rd + 8];
            }
#pragma unroll
            for (int ni = 0; ni < 2; ++ni) {
                const int ce = wn * 16 + ni * 8 + g;
                bfr[ni][0] = sv[buf][kk + t][ce];
                bfr[ni][1] = sv[buf][kk + t + 4][ce];
            }
#pragma unroll
            for (int mi = 0; mi < 2; ++mi)
#pragma unroll
                for (int ni = 0; ni < 2; ++ni)
                    mma8(acc[mi][ni], af[mi], bfr[ni]);
        }
        if (nt < 127) { stage(buf ^ 1); __syncthreads(); buf ^= 1; }
    }

    float* O = g_kv + (size_t)bh * HD * HD;
#pragma unroll
    for (int mi = 0; mi < 2; ++mi)
#pragma unroll
        for (int ni = 0; ni < 2; ++ni) {
            const int d0 = wm * 32 + mi * 16 + g;
            const int e  = wn * 16 + ni * 8 + 2 * t;
            *reinterpret_cast<float2*>(O + (size_t)d0 * HD + e) =
                make_float2(acc[mi][ni][0] * 0.125f, acc[mi][ni][1] * 0.125f);
            *reinterpret_cast<float2*>(O + (size_t)(d0 + 8) * HD + e) =
                make_float2(acc[mi][ni][2] * 0.125f, acc[mi][ni][3] * 0.125f);
        }
}

// ---------------------------------------------------------------------------
// out[bh][n][e] = sum_d q[bh][n][d] * kv[bh][d][e], written to g_o in [B,N,C].
// Grid: (NSEQ/64 row tiles, NBH). Single K=64 stage, no k-loop.
// ---------------------------------------------------------------------------
__global__ __launch_bounds__(256, 1)
void attn_kernel()
{
    __shared__ float sq [64][68];   // [n][d], pad 4
    __shared__ float skv[64][72];   // [d][e], pad 8
    const int bh = blockIdx.y;
    const int n0 = blockIdx.x * 64;
    const float* Qp  = g_q  + (size_t)bh * NSEQ * HD + (size_t)n0 * HD;
    const float* KVp = g_kv + (size_t)bh * HD * HD;

    const int tid = threadIdx.x;
    const int lane = tid & 31, warpId = tid >> 5;
    const int g = lane >> 2, t = lane & 3;
    const int wm = warpId & 1, wn = warpId >> 1;

    const int lrow = tid >> 4;
    const int lc   = (tid & 15) * 4;

#pragma unroll
    for (int i = 0; i < 4; ++i) {
        const int r = lrow + i * 16;
        float4 a = *reinterpret_cast<const float4*>(Qp + (size_t)r * HD + lc);
        *reinterpret_cast<float4*>(&sq[r][lc]) =
            make_float4(tf32r(a.x), tf32r(a.y), tf32r(a.z), tf32r(a.w));
        float4 b = *reinterpret_cast<const float4*>(KVp + (size_t)r * HD + lc);
        *reinterpret_cast<float4*>(&skv[r][lc]) =
            make_float4(tf32r(b.x), tf32r(b.y), tf32r(b.z), tf32r(b.w));
    }
    __syncthreads();

    float acc[2][2][4];
#pragma unroll
    for (int a = 0; a < 2; ++a)
#pragma unroll
        for (int b = 0; b < 2; ++b)
#pragma unroll
            for (int c = 0; c < 4; ++c) acc[a][b][c] = 0.f;

#pragma unroll
    for (int ks = 0; ks < 8; ++ks) {
        const int kk = ks * 8;
        float af[2][4], bfr[2][2];
#pragma unroll
        for (int mi = 0; mi < 2; ++mi) {
            const int rn = wm * 32 + mi * 16 + g;
            af[mi][0] = sq[rn][kk + t];
            af[mi][1] = sq[rn + 8][kk + t];
            af[mi][2] = sq[rn][kk + t + 4];
            af[mi][3] = sq[rn + 8][kk + t + 4];
        }
#pragma unroll
        for (int ni = 0; ni < 2; ++ni) {
            const int ce = wn * 16 + ni * 8 + g;
            bfr[ni][0] = skv[kk + t][ce];
            bfr[ni][1] = skv[kk + t + 4][ce];
        }
#pragma unroll
        for (int mi = 0; mi < 2; ++mi)
#pragma unroll
            for (int ni = 0; ni < 2; ++ni)
                mma8(acc[mi][ni], af[mi], bfr[ni]);
    }

    const int b = bh >> 4, h = bh & (NH - 1);
#pragma unroll
    for (int mi = 0; mi < 2; ++mi)
#pragma unroll
        for (int ni = 0; ni < 2; ++ni) {
            const int nn = n0 + wm * 32 + mi * 16 + g;
            const int e  = wn * 16 + ni * 8 + 2 * t;
            float* p = g_o + ((size_t)(b * NSEQ + nn)) * CDIM + h * HD + e;
            *reinterpret_cast<float2*>(p) =
                make_float2(acc[mi][ni][0], acc[mi][ni][1]);
            *reinterpret_cast<float2*>(p + (size_t)8 * CDIM) =
                make_float2(acc[mi][ni][2], acc[mi][ni][3]);
        }
}

extern "C" void kernel_launch(void* const* d_in, const int* in_sizes, int n_in,
                              void* d_out, int out_size)
{
    (void)in_sizes; (void)n_in; (void)out_size;
    const float* x  = (const float*)d_in[0];
    const float* Wq = (const float*)d_in[1];
    const float* Wk = (const float*)d_in[2];
    const float* Wv = (const float*)d_in[3];
    const float* Wo = (const float*)d_in[4];
    const float* bo = (const float*)d_in[5];
    float* out = (float*)d_out;

    dim3 gproj(B4 * NSEQ / 128, CDIM / 128);   // (128, 8)
    proj_kernel<0><<<gproj, 256>>>(x, Wq, nullptr, nullptr, 0);
    proj_kernel<0><<<gproj, 256>>>(x, Wk, nullptr, nullptr, 1);
    proj_kernel<0><<<gproj, 256>>>(x, Wv, nullptr, nullptr, 2);
    kv_kernel<<<NBH, 256>>>();
    attn_kernel<<<dim3(NSEQ / 64, NBH), 256>>>();
    proj_kernel<1><<<gproj, 256>>>(nullptr, Wo, bo, out, 0);
}